// round 10
// baseline (speedup 1.0000x reference)
#include <cuda_runtime.h>
#include <cuda_bf16.h>
#include <cuda_fp16.h>

typedef unsigned int u32;

constexpr int B_ = 4;
constexpr int M_ = 2048;
constexpr int N_ = 16384;

// coordinate scale: d' = 256*d, r' = r/256; w = r/Σr invariant
constexpr float CSC  = 16.0f;
constexpr float EPS2 = 2.56e-6f;   // 1e-8 * 256

// ---------------- device scratch ----------------
__device__ __half g_x16[(size_t)B_ * N_ * 128];    // [feat_up | interp] fp16
__device__ __half g_fTh[(size_t)B_ * 64 * M_];     // featT fp16 (B,64,M)
__device__ __half g_W1[128 * 128];                 // fp16 weights
__device__ __half g_W2[64 * 128];
__device__ float g_S1[128], g_T1[128], g_S2[64], g_T2[64];

// ---------------- helpers ----------------
__device__ __forceinline__ u32 smem_u32(const void* p) {
    u32 a;
    asm("{ .reg .u64 t; cvta.to.shared.u64 t, %1; cvt.u32.u64 %0, t; }" : "=r"(a) : "l"(p));
    return a;
}
__device__ __forceinline__ u32 cvt_h2(float hi, float lo) {
    u32 r;
    asm("cvt.rn.f16x2.f32 %0, %1, %2;" : "=r"(r) : "f"(hi), "f"(lo));
    return r;
}
__device__ __forceinline__ float frcp(float x) {
    float r;
    asm("rcp.approx.f32 %0, %1;" : "=f"(r) : "f"(x));
    return r;
}
__device__ __forceinline__ void ldsm_x4(u32* r, u32 addr) {
    asm volatile("ldmatrix.sync.aligned.m8n8.x4.shared.b16 {%0, %1, %2, %3}, [%4];"
                 : "=r"(r[0]), "=r"(r[1]), "=r"(r[2]), "=r"(r[3]) : "r"(addr));
}
__device__ __forceinline__ void mma_f16(float* c, const u32* a, u32 b0, u32 b1) {
    asm volatile(
        "mma.sync.aligned.m16n8k16.row.col.f32.f16.f16.f32 "
        "{%0,%1,%2,%3}, {%4,%5,%6,%7}, {%8,%9}, {%0,%1,%2,%3};"
        : "+f"(c[0]), "+f"(c[1]), "+f"(c[2]), "+f"(c[3])
        : "r"(a[0]), "r"(a[1]), "r"(a[2]), "r"(a[3]), "r"(b0), "r"(b1));
}
__device__ __forceinline__ void cp16(u32 dst, const void* src) {
    asm volatile("cp.async.ca.shared.global [%0], [%1], 16;" :: "r"(dst), "l"(src) : "memory");
}
#define CP_COMMIT() asm volatile("cp.async.commit_group;" ::: "memory")
#define CP_WAIT0()  asm volatile("cp.async.wait_group 0;" ::: "memory")

__device__ __forceinline__ float h_hi(float f) {
    return __half2float(__float2half_rn(f));
}

// ============================================================================
// Prep 1: feat_down (B,M,64) f32 -> g_fTh (B,64,M) fp16
// ============================================================================
__global__ __launch_bounds__(256) void prep_feat(const float* __restrict__ feat_down) {
    __shared__ float sT[64][65];
    const int b = blockIdx.y, m0 = blockIdx.x * 64;
    const int tid = threadIdx.x;
#pragma unroll
    for (int j = 0; j < 4; ++j) {
        int i = tid + j * 256;
        int r = i >> 4, c4 = (i & 15) * 4;
        float4 v = *(const float4*)(feat_down + ((size_t)b * M_ + m0 + r) * 64 + c4);
        sT[c4 + 0][r] = v.x; sT[c4 + 1][r] = v.y;
        sT[c4 + 2][r] = v.z; sT[c4 + 3][r] = v.w;
    }
    __syncthreads();
#pragma unroll
    for (int j = 0; j < 8; ++j) {
        int u = tid + j * 256;
        int d = u >> 5, m2 = (u & 31) * 2;
        size_t o = (size_t)(b * 64 + d) * M_ + m0 + m2;
        *(u32*)(g_fTh + o) = cvt_h2(sT[d][m2 + 1], sT[d][m2]);
    }
}

// ============================================================================
// Prep 1b: feat_up (B,N,64) f32 -> g_x16 channels 0-63 fp16
// grid 4096 x 256: one float4 per thread
// ============================================================================
__global__ __launch_bounds__(256) void prep_fu(const float* __restrict__ feat_up) {
    const int idx = blockIdx.x * 256 + threadIdx.x;     // 0 .. 1048575
    const int r = idx >> 4, q = idx & 15;
    float4 v = *(const float4*)(feat_up + (size_t)r * 64 + q * 4);
    u32 p0 = cvt_h2(v.y, v.x);
    u32 p1 = cvt_h2(v.w, v.z);
    *(uint2*)(g_x16 + (size_t)r * 128 + q * 4) = make_uint2(p0, p1);
}

// ============================================================================
// Prep 2: W1/W2 -> fp16 (grid 96x256); block 0 folds BN
// ============================================================================
__global__ __launch_bounds__(256) void prep_w(
    const float* __restrict__ W1, const float* __restrict__ b1,
    const float* __restrict__ g1, const float* __restrict__ be1,
    const float* __restrict__ mu1, const float* __restrict__ va1,
    const float* __restrict__ W2, const float* __restrict__ b2,
    const float* __restrict__ g2, const float* __restrict__ be2,
    const float* __restrict__ mu2, const float* __restrict__ va2)
{
    const int idx = blockIdx.x * 256 + threadIdx.x;
    if (idx < 16384) {
        g_W1[idx] = __float2half_rn(W1[idx]);
    } else {
        int i = idx - 16384;
        g_W2[i] = __float2half_rn(W2[i]);
    }
    if (blockIdx.x == 0) {
        int tid = threadIdx.x;
        if (tid < 128) {
            float s = g1[tid] * rsqrtf(va1[tid] + 1e-5f);
            g_S1[tid] = s;
            g_T1[tid] = (b1[tid] - mu1[tid]) * s + be1[tid];
        }
        if (tid < 64) {
            float s = g2[tid] * rsqrtf(va2[tid] + 1e-5f);
            g_S2[tid] = s;
            g_T2[tid] = (b2[tid] - mu2[tid]) * s + be2[tid];
        }
    }
}

// ============================================================================
// Kernel A: interpolation with tensorized distances (as R9), fp16 output.
// ============================================================================
constexpr int RPB    = 272;                 // feature smem row pitch bytes
constexpr int BT     = 64 * RPB;            // 17408
constexpr int XBP    = 48;                  // coord-row pitch bytes
constexpr int XBT    = 128 * XBP;           // 6144
constexpr int OFF_XB0 = 2 * BT;             // 34816
constexpr int OFF_XB1 = OFF_XB0 + XBT;
constexpr int OFF_UA  = OFF_XB1 + XBT;
constexpr int INTERP_SMEM = OFF_UA + XBT;   // 53248

__global__ __launch_bounds__(256, 2) void interp_kernel(
    const float* __restrict__ xyz_down,
    const float* __restrict__ xyz_up)
{
    extern __shared__ __align__(16) char smem[];
    const u32 sbase = smem_u32(smem);

    const int tid = threadIdx.x, wid = tid >> 5, lane = tid & 31;
    const int b = blockIdx.y, n0 = blockIdx.x * 128;
    const int g = lane >> 2, tg = lane & 3;
    const int r0 = wid * 16;

    auto stageB = [&](int t, int sel) {
        const u32 dstb = sbase + (u32)(sel * BT);
#pragma unroll
        for (int j = 0; j < 4; ++j) {
            int idx = tid + 256 * j;
            int d = idx >> 4, kc = (idx & 15) * 8;
            size_t go = (size_t)(b * 64 + d) * M_ + t * 128 + kc;
            cp16(dstb + (u32)(d * RPB + kc * 2), g_fTh + go);
        }
        CP_COMMIT();
    };
    auto loadC = [&](int t) -> float3 {
        const float* p = xyz_down + ((size_t)b * M_ + t * 128 + tid) * 3;
        return make_float3(p[0], p[1], p[2]);
    };
    auto buildXB = [&](int sel, float3 cr) {
        float bx = cr.x * CSC, by = cr.y * CSC, bz = cr.z * CSC;
        float m2 = bx * bx + by * by + bz * bz + EPS2;
        float cx = -2.f * bx, cy = -2.f * by, cz = -2.f * bz;
        float hx = h_hi(cx), hy = h_hi(cy), hz = h_hi(cz), hm = h_hi(m2);
        u32 w0 = cvt_h2(hy, hx);
        u32 w1 = cvt_h2(hx, hz);
        u32 w2 = cvt_h2(hz, hy);
        u32 w3 = cvt_h2(cy - hy, cx - hx);
        u32 w4 = cvt_h2(1.f, cz - hz);
        u32 w5 = cvt_h2(hm, 1.f);
        u32 w6 = cvt_h2(0.f, m2 - hm);
        u32 dst = sbase + (u32)(OFF_XB0 + sel * XBT + tid * XBP);
        asm volatile("st.shared.v4.b32 [%0], {%1,%2,%3,%4};"
                     :: "r"(dst), "r"(w0), "r"(w1), "r"(w2), "r"(w3));
        asm volatile("st.shared.v4.b32 [%0], {%1,%2,%3,%4};"
                     :: "r"(dst + 16), "r"(w4), "r"(w5), "r"(w6), "r"(0u));
    };

    // ---------------- prologue ----------------
    stageB(0, 0);
    if (tid < 128) {
        const float* p = xyz_up + ((size_t)b * N_ + n0 + tid) * 3;
        float ax = p[0] * CSC, ay = p[1] * CSC, az = p[2] * CSC;
        float n2 = ax * ax + ay * ay + az * az;
        float hx = h_hi(ax), hy = h_hi(ay), hz = h_hi(az), hn = h_hi(n2);
        u32 w0 = cvt_h2(hy, hx);
        u32 w1 = cvt_h2(ax - hx, hz);
        u32 w2 = cvt_h2(az - hz, ay - hy);
        u32 w3 = cvt_h2(hy, hx);
        u32 w4 = cvt_h2(hn, hz);
        u32 w5 = cvt_h2(1.f, n2 - hn);
        u32 w6 = cvt_h2(0.f, 1.f);
        u32 dst = sbase + (u32)(OFF_UA + tid * XBP);
        asm volatile("st.shared.v4.b32 [%0], {%1,%2,%3,%4};"
                     :: "r"(dst), "r"(w0), "r"(w1), "r"(w2), "r"(w3));
        asm volatile("st.shared.v4.b32 [%0], {%1,%2,%3,%4};"
                     :: "r"(dst + 16), "r"(w4), "r"(w5), "r"(w6), "r"(0u));
    }
    float3 cn = make_float3(0.f, 0.f, 0.f);
    if (tid < 128) {
        buildXB(0, loadC(0));
        cn = loadC(1);
    }
    CP_WAIT0();
    __syncthreads();

    u32 aD[4];
    ldsm_x4(aD, sbase + (u32)(OFF_UA + (r0 + (lane & 15)) * XBP + (lane >> 4) * 16));

    float c[8][4];
#pragma unroll
    for (int i = 0; i < 8; ++i)
#pragma unroll
        for (int j = 0; j < 4; ++j) c[i][j] = 0.f;
    float rsA = 0.f, rsB = 0.f;

    const u32 lbaseF = (u32)((lane & 7) * RPB + ((lane >> 3) & 1) * 16
                             + ((lane >> 4) & 1) * 32);
    const u32 lbaseX = (u32)(((lane & 7) + ((lane >> 4) & 1) * 8) * XBP
                             + ((lane >> 3) & 1) * 16);

    for (int t = 0; t < 16; ++t) {
        const int sel = t & 1;
        if (t < 15) {
            stageB(t + 1, sel ^ 1);
            if (tid < 128) buildXB(sel ^ 1, cn);
        }
        if (t < 14 && tid < 128) cn = loadC(t + 2);

        const u32 fsel = sbase + (u32)(sel * BT);
        const u32 xsel = sbase + (u32)(OFF_XB0 + sel * XBT) + lbaseX;

#pragma unroll
        for (int ksp = 0; ksp < 4; ++ksp) {
            u32 ah0[4], ah1[4];
#pragma unroll
            for (int sub = 0; sub < 2; ++sub) {
                const int s = ksp * 2 + sub;
                u32 bx[4];
                ldsm_x4(bx, xsel + (u32)(s * 16 * XBP));
                float cd[8];
#pragma unroll
                for (int i = 0; i < 8; ++i) cd[i] = 0.f;
                mma_f16(cd,     aD, bx[0], bx[1]);
                mma_f16(cd + 4, aD, bx[2], bx[3]);
                float q0 = fminf(frcp(cd[0]), 60000.f);
                float q1 = fminf(frcp(cd[1]), 60000.f);
                float q2 = fminf(frcp(cd[2]), 60000.f);
                float q3 = fminf(frcp(cd[3]), 60000.f);
                float q4 = fminf(frcp(cd[4]), 60000.f);
                float q5 = fminf(frcp(cd[5]), 60000.f);
                float q6 = fminf(frcp(cd[6]), 60000.f);
                float q7 = fminf(frcp(cd[7]), 60000.f);
                rsA += (q0 + q1) + (q4 + q5);
                rsB += (q2 + q3) + (q6 + q7);
                u32* ah = sub ? ah1 : ah0;
                ah[0] = cvt_h2(q1, q0);
                ah[1] = cvt_h2(q3, q2);
                ah[2] = cvt_h2(q5, q4);
                ah[3] = cvt_h2(q7, q6);
            }
            const u32 baddr = fsel + (u32)(ksp * 64) + lbaseF;
            u32 bf[8][4];
#pragma unroll
            for (int nt = 0; nt < 8; ++nt) ldsm_x4(bf[nt], baddr + (u32)(nt * 8 * RPB));
#pragma unroll
            for (int nt = 0; nt < 8; ++nt) mma_f16(c[nt], ah0, bf[nt][0], bf[nt][1]);
#pragma unroll
            for (int nt = 0; nt < 8; ++nt) mma_f16(c[nt], ah1, bf[nt][2], bf[nt][3]);
        }
        if (t < 15) { CP_WAIT0(); __syncthreads(); }
    }

    rsA += __shfl_xor_sync(0xFFFFFFFFu, rsA, 1);
    rsA += __shfl_xor_sync(0xFFFFFFFFu, rsA, 2);
    rsB += __shfl_xor_sync(0xFFFFFFFFu, rsB, 1);
    rsB += __shfl_xor_sync(0xFFFFFFFFu, rsB, 2);
    const float invA = frcp(rsA);
    const float invB = frcp(rsB);

    // fp16 packed output -> g_x16 channels 64-127
    u32* rowA = (u32*)(g_x16 + ((size_t)(b * N_ + n0 + r0 + g)) * 128 + 64);
    u32* rowB = (u32*)(g_x16 + ((size_t)(b * N_ + n0 + r0 + 8 + g)) * 128 + 64);
#pragma unroll
    for (int nt = 0; nt < 8; ++nt) {
        rowA[nt * 4 + tg] = cvt_h2(c[nt][1] * invA, c[nt][0] * invA);
        rowB[nt * 4 + tg] = cvt_h2(c[nt][3] * invB, c[nt][2] * invB);
    }
}

// ============================================================================
// Kernel B: persistent fp16 MLP, smem-staged x-tiles + ldmatrix A-frags.
// grid 256, 2 tiles per CTA.
// ============================================================================
constexpr int SMW1B = 128 * RPB;     // 34816
constexpr int SMW2B = 64 * RPB;      // 17408
constexpr int SMXB  = 128 * RPB;     // 34816
constexpr int MLP_SMEM = SMW1B + SMW2B + SMXB + (128 + 128 + 64 + 64) * 4;  // ~88.6KB
constexpr int NTILES = (B_ * N_) / 128;    // 512

__global__ __launch_bounds__(256) void mlp_kernel(float* __restrict__ out) {
    extern __shared__ __align__(16) char sm[];
    __half* sW1 = (__half*)sm;
    __half* sW2 = (__half*)(sm + SMW1B);
    __half* sX  = (__half*)(sm + SMW1B + SMW2B);
    float* sS1 = (float*)(sm + SMW1B + SMW2B + SMXB);
    float* sT1 = sS1 + 128;
    float* sS2 = sT1 + 128;
    float* sT2 = sS2 + 64;

    const int tid = threadIdx.x, wid = tid >> 5, lane = tid & 31;
    const int g = lane >> 2, tg = lane & 3;
    const int r0 = wid * 16;

    const u32 bW1 = smem_u32(sW1), bW2 = smem_u32(sW2), bX = smem_u32(sX);

    // stage weights once (cp.async)
    for (int i = tid; i < 2048; i += 256) {
        int r = i >> 4, q = i & 15;
        cp16(bW1 + (u32)(r * RPB + q * 16), g_W1 + r * 128 + q * 8);
    }
    for (int i = tid; i < 1024; i += 256) {
        int r = i >> 4, q = i & 15;
        cp16(bW2 + (u32)(r * RPB + q * 16), g_W2 + r * 128 + q * 8);
    }
    CP_COMMIT();
    if (tid < 128) { sS1[tid] = g_S1[tid]; sT1[tid] = g_T1[tid]; }
    if (tid < 64)  { sS2[tid] = g_S2[tid]; sT2[tid] = g_T2[tid]; }

    // B-side lane base (n-tile pairs via x4)
    const u32 lrow4 = (u32)((lane & 7) * RPB + ((lane >> 3) & 1) * 16
                            + ((lane >> 4) & 1) * (8 * RPB));
    // A-side lane base (16 rows x 16 k via x4)
    const u32 larow = (u32)((lane & 15) * RPB + (lane >> 4) * 16);

    for (int tile = blockIdx.x; tile < NTILES; tile += 256) {
        // stage x tile (128 rows x 128 ch fp16, contiguous 256B rows)
        __syncthreads();   // previous tile's A-frags consumed
        for (int i = tid; i < 2048; i += 256) {
            int r = i >> 4, q = i & 15;
            cp16(bX + (u32)(r * RPB + q * 16),
                 g_x16 + ((size_t)tile * 128 + r) * 128 + q * 8);
        }
        CP_COMMIT();
        CP_WAIT0();
        __syncthreads();

        // ---------------- GEMM1 ----------------
        float c1[16][4];
#pragma unroll
        for (int i = 0; i < 16; ++i)
#pragma unroll
            for (int j = 0; j < 4; ++j) c1[i][j] = 0.f;

#pragma unroll
        for (int ks = 0; ks < 8; ++ks) {
            u32 ah[4];
            ldsm_x4(ah, bX + (u32)(r0 * RPB + ks * 32) + larow);
            const u32 koff = (u32)(ks * 32);
#pragma unroll
            for (int ntp = 0; ntp < 8; ++ntp) {
                u32 bf[4];
                ldsm_x4(bf, bW1 + (u32)(ntp * 16 * RPB) + lrow4 + koff);
                mma_f16(c1[2 * ntp],     ah, bf[0], bf[1]);
                mma_f16(c1[2 * ntp + 1], ah, bf[2], bf[3]);
            }
        }

        // BN1 + relu -> A2 fragments
        u32 a2[8][4];
#pragma unroll
        for (int k2 = 0; k2 < 8; ++k2) {
            int nt0 = 2 * k2, nt1 = 2 * k2 + 1;
            int o0 = nt0 * 8 + 2 * tg, o1 = o0 + 1;
            int o2 = nt1 * 8 + 2 * tg, o3 = o2 + 1;
            float hA0 = fmaxf(fmaf(c1[nt0][0], sS1[o0], sT1[o0]), 0.f);
            float hA1 = fmaxf(fmaf(c1[nt0][1], sS1[o1], sT1[o1]), 0.f);
            float hB0 = fmaxf(fmaf(c1[nt0][2], sS1[o0], sT1[o0]), 0.f);
            float hB1 = fmaxf(fmaf(c1[nt0][3], sS1[o1], sT1[o1]), 0.f);
            float hA2 = fmaxf(fmaf(c1[nt1][0], sS1[o2], sT1[o2]), 0.f);
            float hA3 = fmaxf(fmaf(c1[nt1][1], sS1[o3], sT1[o3]), 0.f);
            float hB2 = fmaxf(fmaf(c1[nt1][2], sS1[o2], sT1[o2]), 0.f);
            float hB3 = fmaxf(fmaf(c1[nt1][3], sS1[o3], sT1[o3]), 0.f);
            a2[k2][0] = cvt_h2(hA1, hA0);
            a2[k2][1] = cvt_h2(hB1, hB0);
            a2[k2][2] = cvt_h2(hA3, hA2);
            a2[k2][3] = cvt_h2(hB3, hB2);
        }

        // ---------------- GEMM2 ----------------
        float c2[8][4];
#pragma unroll
        for (int i = 0; i < 8; ++i)
#pragma unroll
            for (int j = 0; j < 4; ++j) c2[i][j] = 0.f;

#pragma unroll
        for (int k2 = 0; k2 < 8; ++k2) {
            const u32 koff = (u32)(k2 * 32);
#pragma unroll
            for (int ntp = 0; ntp < 4; ++ntp) {
                u32 bf[4];
                ldsm_x4(bf, bW2 + (u32)(ntp * 16 * RPB) + lrow4 + koff);
                mma_f16(c2[2 * ntp],     a2[k2], bf[0], bf[1]);
                mma_f16(c2[2 * ntp + 1], a2[k2], bf[2], bf[3]);
            }
        }

        // BN2 + store
        const size_t rowA = (size_t)tile * 128 + r0 + g;
        const size_t rowB = rowA + 8;
        float* oA = out + rowA * 64;
        float* oB = out + rowB * 64;
#pragma unroll
        for (int nt = 0; nt < 8; ++nt) {
            int j0 = nt * 8 + 2 * tg, j1 = j0 + 1;
            *(float2*)(oA + j0) = make_float2(fmaf(c2[nt][0], sS2[j0], sT2[j0]),
                                              fmaf(c2[nt][1], sS2[j1], sT2[j1]));
            *(float2*)(oB + j0) = make_float2(fmaf(c2[nt][2], sS2[j0], sT2[j0]),
                                              fmaf(c2[nt][3], sS2[j1], sT2[j1]));
        }
    }
}

// ============================================================================
extern "C" void kernel_launch(void* const* d_in, const int* in_sizes, int n_in,
                              void* d_out, int out_size)
{
    const float* xyz_down  = (const float*)d_in[0];
    const float* xyz_up    = (const float*)d_in[1];
    const float* feat_down = (const float*)d_in[2];
    const float* feat_up   = (const float*)d_in[3];
    const float* W1  = (const float*)d_in[4];
    const float* b1  = (const float*)d_in[5];
    const float* g1  = (const float*)d_in[6];
    const float* be1 = (const float*)d_in[7];
    const float* mu1 = (const float*)d_in[8];
    const float* va1 = (const float*)d_in[9];
    const float* W2  = (const float*)d_in[10];
    const float* b2  = (const float*)d_in[11];
    const float* g2  = (const float*)d_in[12];
    const float* be2 = (const float*)d_in[13];
    const float* mu2 = (const float*)d_in[14];
    const float* va2 = (const float*)d_in[15];
    float* out = (float*)d_out;

    prep_feat<<<dim3(M_ / 64, B_), 256>>>(feat_down);
    prep_fu<<<4096, 256>>>(feat_up);
    prep_w<<<96, 256>>>(W1, b1, g1, be1, mu1, va1, W2, b2, g2, be2, mu2, va2);

    cudaFuncSetAttribute(interp_kernel,
                         cudaFuncAttributeMaxDynamicSharedMemorySize, INTERP_SMEM);
    interp_kernel<<<dim3(N_ / 128, B_), 256, INTERP_SMEM>>>(xyz_down, xyz_up);

    cudaFuncSetAttribute(mlp_kernel,
                         cudaFuncAttributeMaxDynamicSharedMemorySize, MLP_SMEM);
    mlp_kernel<<<256, 256, MLP_SMEM>>>(out);
}

// round 11
// speedup vs baseline: 1.1104x; 1.1104x over previous
#include <cuda_runtime.h>
#include <cuda_bf16.h>
#include <cuda_fp16.h>

typedef unsigned int u32;

constexpr int B_ = 4;
constexpr int M_ = 2048;
constexpr int N_ = 16384;

// coordinate scale: d' = 256*d, r' = r/256; w = r/Σr invariant
constexpr float CSC  = 16.0f;
constexpr float EPS2 = 2.56e-6f;   // 1e-8 * 256

// ---------------- device scratch ----------------
__device__ __half g_x16[(size_t)B_ * N_ * 128];    // [feat_up | interp] fp16
__device__ __half g_fTh[(size_t)B_ * 64 * M_];     // featT fp16 (B,64,M)
__device__ __half g_W1[128 * 128];                 // fp16 weights
__device__ __half g_W2[64 * 128];
__device__ float g_S1[128], g_T1[128], g_S2[64], g_T2[64];

// ---------------- helpers ----------------
__device__ __forceinline__ u32 smem_u32(const void* p) {
    u32 a;
    asm("{ .reg .u64 t; cvta.to.shared.u64 t, %1; cvt.u32.u64 %0, t; }" : "=r"(a) : "l"(p));
    return a;
}
__device__ __forceinline__ u32 cvt_h2(float hi, float lo) {
    u32 r;
    asm("cvt.rn.f16x2.f32 %0, %1, %2;" : "=r"(r) : "f"(hi), "f"(lo));
    return r;
}
__device__ __forceinline__ u32 cvt_h2_sat(float hi, float lo) {
    u32 r;
    asm("cvt.rn.satfinite.f16x2.f32 %0, %1, %2;" : "=r"(r) : "f"(hi), "f"(lo));
    return r;
}
__device__ __forceinline__ float frcp(float x) {
    float r;
    asm("rcp.approx.f32 %0, %1;" : "=f"(r) : "f"(x));
    return r;
}
__device__ __forceinline__ void ldsm_x4(u32* r, u32 addr) {
    asm volatile("ldmatrix.sync.aligned.m8n8.x4.shared.b16 {%0, %1, %2, %3}, [%4];"
                 : "=r"(r[0]), "=r"(r[1]), "=r"(r[2]), "=r"(r[3]) : "r"(addr));
}
__device__ __forceinline__ void mma_f16(float* c, const u32* a, u32 b0, u32 b1) {
    asm volatile(
        "mma.sync.aligned.m16n8k16.row.col.f32.f16.f16.f32 "
        "{%0,%1,%2,%3}, {%4,%5,%6,%7}, {%8,%9}, {%0,%1,%2,%3};"
        : "+f"(c[0]), "+f"(c[1]), "+f"(c[2]), "+f"(c[3])
        : "r"(a[0]), "r"(a[1]), "r"(a[2]), "r"(a[3]), "r"(b0), "r"(b1));
}
__device__ __forceinline__ void cp16(u32 dst, const void* src) {
    asm volatile("cp.async.ca.shared.global [%0], [%1], 16;" :: "r"(dst), "l"(src) : "memory");
}
#define CP_COMMIT() asm volatile("cp.async.commit_group;" ::: "memory")
#define CP_WAIT0()  asm volatile("cp.async.wait_group 0;" ::: "memory")

__device__ __forceinline__ float h_hi(float f) {
    return __half2float(__float2half_rn(f));
}

// ============================================================================
// Prep 1: feat_down (B,M,64) f32 -> g_fTh (B,64,M) fp16
// ============================================================================
__global__ __launch_bounds__(256) void prep_feat(const float* __restrict__ feat_down) {
    __shared__ float sT[64][65];
    const int b = blockIdx.y, m0 = blockIdx.x * 64;
    const int tid = threadIdx.x;
#pragma unroll
    for (int j = 0; j < 4; ++j) {
        int i = tid + j * 256;
        int r = i >> 4, c4 = (i & 15) * 4;
        float4 v = *(const float4*)(feat_down + ((size_t)b * M_ + m0 + r) * 64 + c4);
        sT[c4 + 0][r] = v.x; sT[c4 + 1][r] = v.y;
        sT[c4 + 2][r] = v.z; sT[c4 + 3][r] = v.w;
    }
    __syncthreads();
#pragma unroll
    for (int j = 0; j < 8; ++j) {
        int u = tid + j * 256;
        int d = u >> 5, m2 = (u & 31) * 2;
        size_t o = (size_t)(b * 64 + d) * M_ + m0 + m2;
        *(u32*)(g_fTh + o) = cvt_h2(sT[d][m2 + 1], sT[d][m2]);
    }
}

// ============================================================================
// Prep 1b: feat_up (B,N,64) f32 -> g_x16 channels 0-63 fp16
// ============================================================================
__global__ __launch_bounds__(256) void prep_fu(const float* __restrict__ feat_up) {
    const int idx = blockIdx.x * 256 + threadIdx.x;
    const int r = idx >> 4, q = idx & 15;
    float4 v = *(const float4*)(feat_up + (size_t)r * 64 + q * 4);
    u32 p0 = cvt_h2(v.y, v.x);
    u32 p1 = cvt_h2(v.w, v.z);
    *(uint2*)(g_x16 + (size_t)r * 128 + q * 4) = make_uint2(p0, p1);
}

// ============================================================================
// Prep 2: W1/W2 -> fp16 (grid 96x256); block 0 folds BN
// ============================================================================
__global__ __launch_bounds__(256) void prep_w(
    const float* __restrict__ W1, const float* __restrict__ b1,
    const float* __restrict__ g1, const float* __restrict__ be1,
    const float* __restrict__ mu1, const float* __restrict__ va1,
    const float* __restrict__ W2, const float* __restrict__ b2,
    const float* __restrict__ g2, const float* __restrict__ be2,
    const float* __restrict__ mu2, const float* __restrict__ va2)
{
    const int idx = blockIdx.x * 256 + threadIdx.x;
    if (idx < 16384) {
        g_W1[idx] = __float2half_rn(W1[idx]);
    } else {
        int i = idx - 16384;
        g_W2[i] = __float2half_rn(W2[i]);
    }
    if (blockIdx.x == 0) {
        int tid = threadIdx.x;
        if (tid < 128) {
            float s = g1[tid] * rsqrtf(va1[tid] + 1e-5f);
            g_S1[tid] = s;
            g_T1[tid] = (b1[tid] - mu1[tid]) * s + be1[tid];
        }
        if (tid < 64) {
            float s = g2[tid] * rsqrtf(va2[tid] + 1e-5f);
            g_S2[tid] = s;
            g_T2[tid] = (b2[tid] - mu2[tid]) * s + be2[tid];
        }
    }
}

// ============================================================================
// Kernel A: interpolation, tensorized distances + ones-channel rsum MMA.
// grid (N/128, B), 256 threads (8 warps x 16 rows), double-buffered cp.async.
// ============================================================================
constexpr int RPB    = 272;                 // feature smem row pitch bytes
constexpr int BT     = 64 * RPB;            // 17408
constexpr int XBP    = 48;                  // coord-row pitch bytes
constexpr int XBT    = 128 * XBP;           // 6144
constexpr int OFF_XB0 = 2 * BT;             // 34816
constexpr int OFF_XB1 = OFF_XB0 + XBT;
constexpr int OFF_UA  = OFF_XB1 + XBT;
constexpr int INTERP_SMEM = OFF_UA + XBT;   // 53248

__global__ __launch_bounds__(256, 2) void interp_kernel(
    const float* __restrict__ xyz_down,
    const float* __restrict__ xyz_up)
{
    extern __shared__ __align__(16) char smem[];
    const u32 sbase = smem_u32(smem);

    const int tid = threadIdx.x, wid = tid >> 5, lane = tid & 31;
    const int b = blockIdx.y, n0 = blockIdx.x * 128;
    const int g = lane >> 2, tg = lane & 3;
    const int r0 = wid * 16;

    auto stageB = [&](int t, int sel) {
        const u32 dstb = sbase + (u32)(sel * BT);
#pragma unroll
        for (int j = 0; j < 4; ++j) {
            int idx = tid + 256 * j;
            int d = idx >> 4, kc = (idx & 15) * 8;
            size_t go = (size_t)(b * 64 + d) * M_ + t * 128 + kc;
            cp16(dstb + (u32)(d * RPB + kc * 2), g_fTh + go);
        }
        CP_COMMIT();
    };
    auto loadC = [&](int t) -> float3 {
        const float* p = xyz_down + ((size_t)b * M_ + t * 128 + tid) * 3;
        return make_float3(p[0], p[1], p[2]);
    };
    auto buildXB = [&](int sel, float3 cr) {
        float bx = cr.x * CSC, by = cr.y * CSC, bz = cr.z * CSC;
        float m2 = bx * bx + by * by + bz * bz + EPS2;
        float cx = -2.f * bx, cy = -2.f * by, cz = -2.f * bz;
        float hx = h_hi(cx), hy = h_hi(cy), hz = h_hi(cz), hm = h_hi(m2);
        u32 w0 = cvt_h2(hy, hx);
        u32 w1 = cvt_h2(hx, hz);
        u32 w2 = cvt_h2(hz, hy);
        u32 w3 = cvt_h2(cy - hy, cx - hx);
        u32 w4 = cvt_h2(1.f, cz - hz);
        u32 w5 = cvt_h2(hm, 1.f);
        u32 w6 = cvt_h2(0.f, m2 - hm);
        u32 dst = sbase + (u32)(OFF_XB0 + sel * XBT + tid * XBP);
        asm volatile("st.shared.v4.b32 [%0], {%1,%2,%3,%4};"
                     :: "r"(dst), "r"(w0), "r"(w1), "r"(w2), "r"(w3));
        asm volatile("st.shared.v4.b32 [%0], {%1,%2,%3,%4};"
                     :: "r"(dst + 16), "r"(w4), "r"(w5), "r"(w6), "r"(0u));
    };

    // ---------------- prologue ----------------
    stageB(0, 0);
    if (tid < 128) {
        const float* p = xyz_up + ((size_t)b * N_ + n0 + tid) * 3;
        float ax = p[0] * CSC, ay = p[1] * CSC, az = p[2] * CSC;
        float n2 = ax * ax + ay * ay + az * az;
        float hx = h_hi(ax), hy = h_hi(ay), hz = h_hi(az), hn = h_hi(n2);
        u32 w0 = cvt_h2(hy, hx);
        u32 w1 = cvt_h2(ax - hx, hz);
        u32 w2 = cvt_h2(az - hz, ay - hy);
        u32 w3 = cvt_h2(hy, hx);
        u32 w4 = cvt_h2(hn, hz);
        u32 w5 = cvt_h2(1.f, n2 - hn);
        u32 w6 = cvt_h2(0.f, 1.f);
        u32 dst = sbase + (u32)(OFF_UA + tid * XBP);
        asm volatile("st.shared.v4.b32 [%0], {%1,%2,%3,%4};"
                     :: "r"(dst), "r"(w0), "r"(w1), "r"(w2), "r"(w3));
        asm volatile("st.shared.v4.b32 [%0], {%1,%2,%3,%4};"
                     :: "r"(dst + 16), "r"(w4), "r"(w5), "r"(w6), "r"(0u));
    }
    float3 cn = make_float3(0.f, 0.f, 0.f);
    if (tid < 128) {
        buildXB(0, loadC(0));
        cn = loadC(1);
    }
    CP_WAIT0();
    __syncthreads();

    u32 aD[4];
    ldsm_x4(aD, sbase + (u32)(OFF_UA + (r0 + (lane & 15)) * XBP + (lane >> 4) * 16));

    float c[8][4];
#pragma unroll
    for (int i = 0; i < 8; ++i)
#pragma unroll
        for (int j = 0; j < 4; ++j) c[i][j] = 0.f;
    // ones-channel accumulator: after loop c9[0]=rsA, c9[2]=rsB (tg==0 lanes)
    float c9[4] = {0.f, 0.f, 0.f, 0.f};
    const u32 bone = (g == 0) ? 0x3C003C00u : 0u;   // B-frag of all-ones n-col 0

    const u32 lbaseF = (u32)((lane & 7) * RPB + ((lane >> 3) & 1) * 16
                             + ((lane >> 4) & 1) * 32);
    const u32 lbaseX = (u32)(((lane & 7) + ((lane >> 4) & 1) * 8) * XBP
                             + ((lane >> 3) & 1) * 16);

    for (int t = 0; t < 16; ++t) {
        const int sel = t & 1;
        if (t < 15) {
            stageB(t + 1, sel ^ 1);
            if (tid < 128) buildXB(sel ^ 1, cn);
        }
        if (t < 14 && tid < 128) cn = loadC(t + 2);

        const u32 fsel = sbase + (u32)(sel * BT);
        const u32 xsel = sbase + (u32)(OFF_XB0 + sel * XBT) + lbaseX;

#pragma unroll
        for (int ksp = 0; ksp < 4; ++ksp) {
            u32 ah0[4], ah1[4];
#pragma unroll
            for (int sub = 0; sub < 2; ++sub) {
                const int s = ksp * 2 + sub;
                u32 bx[4];
                ldsm_x4(bx, xsel + (u32)(s * 16 * XBP));
                float cd[8];
#pragma unroll
                for (int i = 0; i < 8; ++i) cd[i] = 0.f;
                mma_f16(cd,     aD, bx[0], bx[1]);
                mma_f16(cd + 4, aD, bx[2], bx[3]);
                float q0 = frcp(cd[0]);
                float q1 = frcp(cd[1]);
                float q2 = frcp(cd[2]);
                float q3 = frcp(cd[3]);
                float q4 = frcp(cd[4]);
                float q5 = frcp(cd[5]);
                float q6 = frcp(cd[6]);
                float q7 = frcp(cd[7]);
                u32* ah = sub ? ah1 : ah0;
                ah[0] = cvt_h2_sat(q1, q0);
                ah[1] = cvt_h2_sat(q3, q2);
                ah[2] = cvt_h2_sat(q5, q4);
                ah[3] = cvt_h2_sat(q7, q6);
            }
            const u32 baddr = fsel + (u32)(ksp * 64) + lbaseF;
            u32 bf[8][4];
#pragma unroll
            for (int nt = 0; nt < 8; ++nt) ldsm_x4(bf[nt], baddr + (u32)(nt * 8 * RPB));
#pragma unroll
            for (int nt = 0; nt < 8; ++nt) mma_f16(c[nt], ah0, bf[nt][0], bf[nt][1]);
            mma_f16(c9, ah0, bone, bone);
#pragma unroll
            for (int nt = 0; nt < 8; ++nt) mma_f16(c[nt], ah1, bf[nt][2], bf[nt][3]);
            mma_f16(c9, ah1, bone, bone);
        }
        if (t < 15) { CP_WAIT0(); __syncthreads(); }
    }

    // broadcast rsum from tg==0 lane of each quad
    const float rsA = __shfl_sync(0xFFFFFFFFu, c9[0], lane & 28);
    const float rsB = __shfl_sync(0xFFFFFFFFu, c9[2], lane & 28);
    const float invA = frcp(rsA);
    const float invB = frcp(rsB);

    // fp16 packed output -> g_x16 channels 64-127
    u32* rowA = (u32*)(g_x16 + ((size_t)(b * N_ + n0 + r0 + g)) * 128 + 64);
    u32* rowB = (u32*)(g_x16 + ((size_t)(b * N_ + n0 + r0 + 8 + g)) * 128 + 64);
#pragma unroll
    for (int nt = 0; nt < 8; ++nt) {
        rowA[nt * 4 + tg] = cvt_h2(c[nt][1] * invA, c[nt][0] * invA);
        rowB[nt * 4 + tg] = cvt_h2(c[nt][3] * invB, c[nt][2] * invB);
    }
}

// ============================================================================
// Kernel B: fp16 MLP, grid 512 (one 128-row tile per CTA), single-stage smem.
// ============================================================================
constexpr int SMW1B = 128 * RPB;     // 34816
constexpr int SMW2B = 64 * RPB;      // 17408
constexpr int SMXB  = 128 * RPB;     // 34816
constexpr int MLP_SMEM = SMW1B + SMW2B + SMXB + (128 + 128 + 64 + 64) * 4;  // ~88.6KB

__global__ __launch_bounds__(256) void mlp_kernel(float* __restrict__ out) {
    extern __shared__ __align__(16) char sm[];
    __half* sW1 = (__half*)sm;
    __half* sW2 = (__half*)(sm + SMW1B);
    __half* sX  = (__half*)(sm + SMW1B + SMW2B);
    float* sS1 = (float*)(sm + SMW1B + SMW2B + SMXB);
    float* sT1 = sS1 + 128;
    float* sS2 = sT1 + 128;
    float* sT2 = sS2 + 64;

    const int tid = threadIdx.x, wid = tid >> 5, lane = tid & 31;
    const int g = lane >> 2, tg = lane & 3;
    const int r0 = wid * 16;
    const int tile = blockIdx.x;

    const u32 bW1 = smem_u32(sW1), bW2 = smem_u32(sW2), bX = smem_u32(sX);

    // single staging phase: weights + x tile + BN consts
    for (int i = tid; i < 2048; i += 256) {
        int r = i >> 4, q = i & 15;
        cp16(bW1 + (u32)(r * RPB + q * 16), g_W1 + r * 128 + q * 8);
    }
    for (int i = tid; i < 1024; i += 256) {
        int r = i >> 4, q = i & 15;
        cp16(bW2 + (u32)(r * RPB + q * 16), g_W2 + r * 128 + q * 8);
    }
    for (int i = tid; i < 2048; i += 256) {
        int r = i >> 4, q = i & 15;
        cp16(bX + (u32)(r * RPB + q * 16),
             g_x16 + ((size_t)tile * 128 + r) * 128 + q * 8);
    }
    CP_COMMIT();
    if (tid < 128) { sS1[tid] = g_S1[tid]; sT1[tid] = g_T1[tid]; }
    if (tid < 64)  { sS2[tid] = g_S2[tid]; sT2[tid] = g_T2[tid]; }
    CP_WAIT0();
    __syncthreads();

    const u32 lrow4 = (u32)((lane & 7) * RPB + ((lane >> 3) & 1) * 16
                            + ((lane >> 4) & 1) * (8 * RPB));
    const u32 larow = (u32)((lane & 15) * RPB + (lane >> 4) * 16);

    // ---------------- GEMM1 ----------------
    float c1[16][4];
#pragma unroll
    for (int i = 0; i < 16; ++i)
#pragma unroll
        for (int j = 0; j < 4; ++j) c1[i][j] = 0.f;

#pragma unroll
    for (int ks = 0; ks < 8; ++ks) {
        u32 ah[4];
        ldsm_x4(ah, bX + (u32)(r0 * RPB + ks * 32) + larow);
        const u32 koff = (u32)(ks * 32);
#pragma unroll
        for (int ntp = 0; ntp < 8; ++ntp) {
            u32 bf[4];
            ldsm_x4(bf, bW1 + (u32)(ntp * 16 * RPB) + lrow4 + koff);
            mma_f16(c1[2 * ntp],     ah, bf[0], bf[1]);
            mma_f16(c1[2 * ntp + 1], ah, bf[2], bf[3]);
        }
    }

    // BN1 + relu -> A2 fragments
    u32 a2[8][4];
#pragma unroll
    for (int k2 = 0; k2 < 8; ++k2) {
        int nt0 = 2 * k2, nt1 = 2 * k2 + 1;
        int o0 = nt0 * 8 + 2 * tg, o1 = o0 + 1;
        int o2 = nt1 * 8 + 2 * tg, o3 = o2 + 1;
        float hA0 = fmaxf(fmaf(c1[nt0][0], sS1[o0], sT1[o0]), 0.f);
        float hA1 = fmaxf(fmaf(c1[nt0][1], sS1[o1], sT1[o1]), 0.f);
        float hB0 = fmaxf(fmaf(c1[nt0][2], sS1[o0], sT1[o0]), 0.f);
        float hB1 = fmaxf(fmaf(c1[nt0][3], sS1[o1], sT1[o1]), 0.f);
        float hA2 = fmaxf(fmaf(c1[nt1][0], sS1[o2], sT1[o2]), 0.f);
        float hA3 = fmaxf(fmaf(c1[nt1][1], sS1[o3], sT1[o3]), 0.f);
        float hB2 = fmaxf(fmaf(c1[nt1][2], sS1[o2], sT1[o2]), 0.f);
        float hB3 = fmaxf(fmaf(c1[nt1][3], sS1[o3], sT1[o3]), 0.f);
        a2[k2][0] = cvt_h2(hA1, hA0);
        a2[k2][1] = cvt_h2(hB1, hB0);
        a2[k2][2] = cvt_h2(hA3, hA2);
        a2[k2][3] = cvt_h2(hB3, hB2);
    }

    // ---------------- GEMM2 ----------------
    float c2[8][4];
#pragma unroll
    for (int i = 0; i < 8; ++i)
#pragma unroll
        for (int j = 0; j < 4; ++j) c2[i][j] = 0.f;

#pragma unroll
    for (int k2 = 0; k2 < 8; ++k2) {
        const u32 koff = (u32)(k2 * 32);
#pragma unroll
        for (int ntp = 0; ntp < 4; ++ntp) {
            u32 bf[4];
            ldsm_x4(bf, bW2 + (u32)(ntp * 16 * RPB) + lrow4 + koff);
            mma_f16(c2[2 * ntp],     a2[k2], bf[0], bf[1]);
            mma_f16(c2[2 * ntp + 1], a2[k2], bf[2], bf[3]);
        }
    }

    // BN2 + store
    const size_t rowA = (size_t)tile * 128 + r0 + g;
    const size_t rowB = rowA + 8;
    float* oA = out + rowA * 64;
    float* oB = out + rowB * 64;
#pragma unroll
    for (int nt = 0; nt < 8; ++nt) {
        int j0 = nt * 8 + 2 * tg, j1 = j0 + 1;
        *(float2*)(oA + j0) = make_float2(fmaf(c2[nt][0], sS2[j0], sT2[j0]),
                                          fmaf(c2[nt][1], sS2[j1], sT2[j1]));
        *(float2*)(oB + j0) = make_float2(fmaf(c2[nt][2], sS2[j0], sT2[j0]),
                                          fmaf(c2[nt][3], sS2[j1], sT2[j1]));
    }
}

// ============================================================================
extern "C" void kernel_launch(void* const* d_in, const int* in_sizes, int n_in,
                              void* d_out, int out_size)
{
    const float* xyz_down  = (const float*)d_in[0];
    const float* xyz_up    = (const float*)d_in[1];
    const float* feat_down = (const float*)d_in[2];
    const float* feat_up   = (const float*)d_in[3];
    const float* W1  = (const float*)d_in[4];
    const float* b1  = (const float*)d_in[5];
    const float* g1  = (const float*)d_in[6];
    const float* be1 = (const float*)d_in[7];
    const float* mu1 = (const float*)d_in[8];
    const float* va1 = (const float*)d_in[9];
    const float* W2  = (const float*)d_in[10];
    const float* b2  = (const float*)d_in[11];
    const float* g2  = (const float*)d_in[12];
    const float* be2 = (const float*)d_in[13];
    const float* mu2 = (const float*)d_in[14];
    const float* va2 = (const float*)d_in[15];
    float* out = (float*)d_out;

    prep_feat<<<dim3(M_ / 64, B_), 256>>>(feat_down);
    prep_fu<<<4096, 256>>>(feat_up);
    prep_w<<<96, 256>>>(W1, b1, g1, be1, mu1, va1, W2, b2, g2, be2, mu2, va2);

    cudaFuncSetAttribute(interp_kernel,
                         cudaFuncAttributeMaxDynamicSharedMemorySize, INTERP_SMEM);
    interp_kernel<<<dim3(N_ / 128, B_), 256, INTERP_SMEM>>>(xyz_down, xyz_up);

    cudaFuncSetAttribute(mlp_kernel,
                         cudaFuncAttributeMaxDynamicSharedMemorySize, MLP_SMEM);
    mlp_kernel<<<512, 256, MLP_SMEM>>>(out);
}

// round 15
// speedup vs baseline: 1.1360x; 1.0231x over previous
#include <cuda_runtime.h>
#include <cuda_bf16.h>
#include <cuda_fp16.h>

typedef unsigned int u32;

constexpr int B_ = 4;
constexpr int M_ = 2048;
constexpr int N_ = 16384;

// coordinate scale: d' = 256*d, r' = r/256; w = r/Σr invariant
constexpr float CSC  = 16.0f;
constexpr float EPS2 = 2.56e-6f;   // 1e-8 * 256

// ---------------- device scratch ----------------
__device__ __half g_x16[(size_t)B_ * N_ * 128];    // [feat_up | interp] fp16
__device__ __half g_fTh[(size_t)B_ * 64 * M_];     // featT fp16 (B,64,M)
__device__ __half g_W1[128 * 128];                 // fp16 weights
__device__ __half g_W2[64 * 128];
__device__ float g_S1[128], g_T1[128], g_S2[64], g_T2[64];

// ---------------- helpers ----------------
__device__ __forceinline__ u32 smem_u32(const void* p) {
    u32 a;
    asm("{ .reg .u64 t; cvta.to.shared.u64 t, %1; cvt.u32.u64 %0, t; }" : "=r"(a) : "l"(p));
    return a;
}
__device__ __forceinline__ u32 cvt_h2(float hi, float lo) {
    u32 r;
    asm("cvt.rn.f16x2.f32 %0, %1, %2;" : "=r"(r) : "f"(hi), "f"(lo));
    return r;
}
__device__ __forceinline__ u32 cvt_h2_sat(float hi, float lo) {
    u32 r;
    asm("cvt.rn.satfinite.f16x2.f32 %0, %1, %2;" : "=r"(r) : "f"(hi), "f"(lo));
    return r;
}
__device__ __forceinline__ float frcp(float x) {
    float r;
    asm("rcp.approx.f32 %0, %1;" : "=f"(r) : "f"(x));
    return r;
}
__device__ __forceinline__ void ldsm_x4(u32* r, u32 addr) {
    asm volatile("ldmatrix.sync.aligned.m8n8.x4.shared.b16 {%0, %1, %2, %3}, [%4];"
                 : "=r"(r[0]), "=r"(r[1]), "=r"(r[2]), "=r"(r[3]) : "r"(addr));
}
__device__ __forceinline__ void mma_f16(float* c, const u32* a, u32 b0, u32 b1) {
    asm volatile(
        "mma.sync.aligned.m16n8k16.row.col.f32.f16.f16.f32 "
        "{%0,%1,%2,%3}, {%4,%5,%6,%7}, {%8,%9}, {%0,%1,%2,%3};"
        : "+f"(c[0]), "+f"(c[1]), "+f"(c[2]), "+f"(c[3])
        : "r"(a[0]), "r"(a[1]), "r"(a[2]), "r"(a[3]), "r"(b0), "r"(b1));
}
// zero-C form: D = A*B + {z,z,z,z}; z stays in one loop-invariant register
__device__ __forceinline__ void mma_f16_zc(float* d, const u32* a, u32 b0, u32 b1, float z) {
    asm volatile(
        "mma.sync.aligned.m16n8k16.row.col.f32.f16.f16.f32 "
        "{%0,%1,%2,%3}, {%4,%5,%6,%7}, {%8,%9}, {%10,%10,%10,%10};"
        : "=f"(d[0]), "=f"(d[1]), "=f"(d[2]), "=f"(d[3])
        : "r"(a[0]), "r"(a[1]), "r"(a[2]), "r"(a[3]), "r"(b0), "r"(b1), "f"(z));
}
__device__ __forceinline__ void cp16(u32 dst, const void* src) {
    asm volatile("cp.async.ca.shared.global [%0], [%1], 16;" :: "r"(dst), "l"(src) : "memory");
}
#define CP_COMMIT() asm volatile("cp.async.commit_group;" ::: "memory")
#define CP_WAIT0()  asm volatile("cp.async.wait_group 0;" ::: "memory")

__device__ __forceinline__ float h_hi(float f) {
    return __half2float(__float2half_rn(f));
}

// ============================================================================
// Prep 1: feat_down (B,M,64) f32 -> g_fTh (B,64,M) fp16
// ============================================================================
__global__ __launch_bounds__(256) void prep_feat(const float* __restrict__ feat_down) {
    __shared__ float sT[64][65];
    const int b = blockIdx.y, m0 = blockIdx.x * 64;
    const int tid = threadIdx.x;
#pragma unroll
    for (int j = 0; j < 4; ++j) {
        int i = tid + j * 256;
        int r = i >> 4, c4 = (i & 15) * 4;
        float4 v = *(const float4*)(feat_down + ((size_t)b * M_ + m0 + r) * 64 + c4);
        sT[c4 + 0][r] = v.x; sT[c4 + 1][r] = v.y;
        sT[c4 + 2][r] = v.z; sT[c4 + 3][r] = v.w;
    }
    __syncthreads();
#pragma unroll
    for (int j = 0; j < 8; ++j) {
        int u = tid + j * 256;
        int d = u >> 5, m2 = (u & 31) * 2;
        size_t o = (size_t)(b * 64 + d) * M_ + m0 + m2;
        *(u32*)(g_fTh + o) = cvt_h2(sT[d][m2 + 1], sT[d][m2]);
    }
}

// ============================================================================
// Prep 1b: feat_up (B,N,64) f32 -> g_x16 channels 0-63 fp16
// ============================================================================
__global__ __launch_bounds__(256) void prep_fu(const float* __restrict__ feat_up) {
    const int idx = blockIdx.x * 256 + threadIdx.x;
    const int r = idx >> 4, q = idx & 15;
    float4 v = *(const float4*)(feat_up + (size_t)r * 64 + q * 4);
    u32 p0 = cvt_h2(v.y, v.x);
    u32 p1 = cvt_h2(v.w, v.z);
    *(uint2*)(g_x16 + (size_t)r * 128 + q * 4) = make_uint2(p0, p1);
}

// ============================================================================
// Prep 2: W1/W2 -> fp16 (grid 96x256); block 0 folds BN
// ============================================================================
__global__ __launch_bounds__(256) void prep_w(
    const float* __restrict__ W1, const float* __restrict__ b1,
    const float* __restrict__ g1, const float* __restrict__ be1,
    const float* __restrict__ mu1, const float* __restrict__ va1,
    const float* __restrict__ W2, const float* __restrict__ b2,
    const float* __restrict__ g2, const float* __restrict__ be2,
    const float* __restrict__ mu2, const float* __restrict__ va2)
{
    const int idx = blockIdx.x * 256 + threadIdx.x;
    if (idx < 16384) {
        g_W1[idx] = __float2half_rn(W1[idx]);
    } else {
        int i = idx - 16384;
        g_W2[i] = __float2half_rn(W2[i]);
    }
    if (blockIdx.x == 0) {
        int tid = threadIdx.x;
        if (tid < 128) {
            float s = g1[tid] * rsqrtf(va1[tid] + 1e-5f);
            g_S1[tid] = s;
            g_T1[tid] = (b1[tid] - mu1[tid]) * s + be1[tid];
        }
        if (tid < 64) {
            float s = g2[tid] * rsqrtf(va2[tid] + 1e-5f);
            g_S2[tid] = s;
            g_T2[tid] = (b2[tid] - mu2[tid]) * s + be2[tid];
        }
    }
}

// ============================================================================
// Kernel A: interpolation, 128 threads (4 warps x 32 rows), tensorized
// distances + ones-channel rsum, shared B-fragments across row-frags.
// ============================================================================
constexpr int RPB    = 272;                 // feature smem row pitch bytes
constexpr int BT     = 64 * RPB;            // 17408
constexpr int XBP    = 48;                  // coord-row pitch bytes
constexpr int XBT    = 128 * XBP;           // 6144
constexpr int OFF_XB0 = 2 * BT;             // 34816
constexpr int OFF_XB1 = OFF_XB0 + XBT;
constexpr int OFF_UA  = OFF_XB1 + XBT;
constexpr int INTERP_SMEM = OFF_UA + XBT;   // 53248

__global__ __launch_bounds__(128, 2) void interp_kernel(
    const float* __restrict__ xyz_down,
    const float* __restrict__ xyz_up)
{
    extern __shared__ __align__(16) char smem[];
    const u32 sbase = smem_u32(smem);

    const int tid = threadIdx.x, wid = tid >> 5, lane = tid & 31;
    const int b = blockIdx.y, n0 = blockIdx.x * 128;
    const int g = lane >> 2, tg = lane & 3;
    const int r0 = wid * 32;

    auto stageB = [&](int t, int sel) {
        const u32 dstb = sbase + (u32)(sel * BT);
#pragma unroll
        for (int j = 0; j < 8; ++j) {
            int idx = tid + 128 * j;
            int d = idx >> 4, kc = (idx & 15) * 8;
            size_t go = (size_t)(b * 64 + d) * M_ + t * 128 + kc;
            cp16(dstb + (u32)(d * RPB + kc * 2), g_fTh + go);
        }
        CP_COMMIT();
    };
    auto loadC = [&](int t) -> float3 {
        const float* p = xyz_down + ((size_t)b * M_ + t * 128 + tid) * 3;
        return make_float3(p[0], p[1], p[2]);
    };
    auto buildXB = [&](int sel, float3 cr) {
        float bx = cr.x * CSC, by = cr.y * CSC, bz = cr.z * CSC;
        float m2 = bx * bx + by * by + bz * bz + EPS2;
        float cx = -2.f * bx, cy = -2.f * by, cz = -2.f * bz;
        float hx = h_hi(cx), hy = h_hi(cy), hz = h_hi(cz), hm = h_hi(m2);
        u32 w0 = cvt_h2(hy, hx);
        u32 w1 = cvt_h2(hx, hz);
        u32 w2 = cvt_h2(hz, hy);
        u32 w3 = cvt_h2(cy - hy, cx - hx);
        u32 w4 = cvt_h2(1.f, cz - hz);
        u32 w5 = cvt_h2(hm, 1.f);
        u32 w6 = cvt_h2(0.f, m2 - hm);
        u32 dst = sbase + (u32)(OFF_XB0 + sel * XBT + tid * XBP);
        asm volatile("st.shared.v4.b32 [%0], {%1,%2,%3,%4};"
                     :: "r"(dst), "r"(w0), "r"(w1), "r"(w2), "r"(w3));
        asm volatile("st.shared.v4.b32 [%0], {%1,%2,%3,%4};"
                     :: "r"(dst + 16), "r"(w4), "r"(w5), "r"(w6), "r"(0u));
    };

    // ---------------- prologue ----------------
    stageB(0, 0);
    {
        // up-point row (A operand of the distance GEMM) — one per thread
        const float* p = xyz_up + ((size_t)b * N_ + n0 + tid) * 3;
        float ax = p[0] * CSC, ay = p[1] * CSC, az = p[2] * CSC;
        float n2 = ax * ax + ay * ay + az * az;
        float hx = h_hi(ax), hy = h_hi(ay), hz = h_hi(az), hn = h_hi(n2);
        u32 w0 = cvt_h2(hy, hx);
        u32 w1 = cvt_h2(ax - hx, hz);
        u32 w2 = cvt_h2(az - hz, ay - hy);
        u32 w3 = cvt_h2(hy, hx);
        u32 w4 = cvt_h2(hn, hz);
        u32 w5 = cvt_h2(1.f, n2 - hn);
        u32 w6 = cvt_h2(0.f, 1.f);
        u32 dst = sbase + (u32)(OFF_UA + tid * XBP);
        asm volatile("st.shared.v4.b32 [%0], {%1,%2,%3,%4};"
                     :: "r"(dst), "r"(w0), "r"(w1), "r"(w2), "r"(w3));
        asm volatile("st.shared.v4.b32 [%0], {%1,%2,%3,%4};"
                     :: "r"(dst + 16), "r"(w4), "r"(w5), "r"(w6), "r"(0u));
    }
    float3 cn;
    buildXB(0, loadC(0));
    cn = loadC(1);
    CP_WAIT0();
    __syncthreads();

    // constant distance-A fragments: rows r0..r0+15 and r0+16..r0+31
    u32 aD0[4], aD1[4];
    ldsm_x4(aD0, sbase + (u32)(OFF_UA + (r0 + (lane & 15)) * XBP + (lane >> 4) * 16));
    ldsm_x4(aD1, sbase + (u32)(OFF_UA + (r0 + 16 + (lane & 15)) * XBP + (lane >> 4) * 16));

    float c0[8][4], c1[8][4];
#pragma unroll
    for (int i = 0; i < 8; ++i)
#pragma unroll
        for (int j = 0; j < 4; ++j) { c0[i][j] = 0.f; c1[i][j] = 0.f; }
    float c9a[4] = {0.f, 0.f, 0.f, 0.f};
    float c9b[4] = {0.f, 0.f, 0.f, 0.f};
    const u32 bone = (g == 0) ? 0x3C003C00u : 0u;   // B-frag of all-ones n-col 0
    const float fz = 0.f;

    const u32 lbaseF = (u32)((lane & 7) * RPB + ((lane >> 3) & 1) * 16
                             + ((lane >> 4) & 1) * 32);
    const u32 lbaseX = (u32)(((lane & 7) + ((lane >> 4) & 1) * 8) * XBP
                             + ((lane >> 3) & 1) * 16);

    for (int t = 0; t < 16; ++t) {
        const int sel = t & 1;
        if (t < 15) {
            stageB(t + 1, sel ^ 1);
            buildXB(sel ^ 1, cn);
        }
        if (t < 14) cn = loadC(t + 2);

        const u32 fsel = sbase + (u32)(sel * BT);
        const u32 xsel = sbase + (u32)(OFF_XB0 + sel * XBT) + lbaseX;

#pragma unroll
        for (int ksp = 0; ksp < 4; ++ksp) {
            u32 a00[4], a01[4], a10[4], a11[4];   // a<frag><sub>
#pragma unroll
            for (int sub = 0; sub < 2; ++sub) {
                const int s = ksp * 2 + sub;
                u32 bx[4];
                ldsm_x4(bx, xsel + (u32)(s * 16 * XBP));
                float cd0[8], cd1[8];
                mma_f16_zc(cd0,     aD0, bx[0], bx[1], fz);
                mma_f16_zc(cd0 + 4, aD0, bx[2], bx[3], fz);
                mma_f16_zc(cd1,     aD1, bx[0], bx[1], fz);
                mma_f16_zc(cd1 + 4, aD1, bx[2], bx[3], fz);
                u32* af0 = sub ? a01 : a00;
                u32* af1 = sub ? a11 : a10;
                af0[0] = cvt_h2_sat(frcp(cd0[1]), frcp(cd0[0]));
                af0[1] = cvt_h2_sat(frcp(cd0[3]), frcp(cd0[2]));
                af0[2] = cvt_h2_sat(frcp(cd0[5]), frcp(cd0[4]));
                af0[3] = cvt_h2_sat(frcp(cd0[7]), frcp(cd0[6]));
                af1[0] = cvt_h2_sat(frcp(cd1[1]), frcp(cd1[0]));
                af1[1] = cvt_h2_sat(frcp(cd1[3]), frcp(cd1[2]));
                af1[2] = cvt_h2_sat(frcp(cd1[5]), frcp(cd1[4]));
                af1[3] = cvt_h2_sat(frcp(cd1[7]), frcp(cd1[6]));
            }
            const u32 baddr = fsel + (u32)(ksp * 64) + lbaseF;
            u32 bf[8][4];
#pragma unroll
            for (int nt = 0; nt < 8; ++nt) ldsm_x4(bf[nt], baddr + (u32)(nt * 8 * RPB));
#pragma unroll
            for (int nt = 0; nt < 8; ++nt) {
                mma_f16(c0[nt], a00, bf[nt][0], bf[nt][1]);
                mma_f16(c1[nt], a10, bf[nt][0], bf[nt][1]);
            }
            mma_f16(c9a, a00, bone, bone);
            mma_f16(c9b, a10, bone, bone);
#pragma unroll
            for (int nt = 0; nt < 8; ++nt) {
                mma_f16(c0[nt], a01, bf[nt][2], bf[nt][3]);
                mma_f16(c1[nt], a11, bf[nt][2], bf[nt][3]);
            }
            mma_f16(c9a, a01, bone, bone);
            mma_f16(c9b, a11, bone, bone);
        }
        if (t < 15) { CP_WAIT0(); __syncthreads(); }
    }

    // broadcast rsum from tg==0 lane of each quad
    const float rsA0 = __shfl_sync(0xFFFFFFFFu, c9a[0], lane & 28);
    const float rsB0 = __shfl_sync(0xFFFFFFFFu, c9a[2], lane & 28);
    const float rsA1 = __shfl_sync(0xFFFFFFFFu, c9b[0], lane & 28);
    const float rsB1 = __shfl_sync(0xFFFFFFFFu, c9b[2], lane & 28);
    const float iA0 = frcp(rsA0), iB0 = frcp(rsB0);
    const float iA1 = frcp(rsA1), iB1 = frcp(rsB1);

    // fp16 packed output -> g_x16 channels 64-127
    u32* rA0 = (u32*)(g_x16 + ((size_t)(b * N_ + n0 + r0 + g)) * 128 + 64);
    u32* rB0 = (u32*)(g_x16 + ((size_t)(b * N_ + n0 + r0 + 8 + g)) * 128 + 64);
    u32* rA1 = (u32*)(g_x16 + ((size_t)(b * N_ + n0 + r0 + 16 + g)) * 128 + 64);
    u32* rB1 = (u32*)(g_x16 + ((size_t)(b * N_ + n0 + r0 + 24 + g)) * 128 + 64);
#pragma unroll
    for (int nt = 0; nt < 8; ++nt) {
        rA0[nt * 4 + tg] = cvt_h2(c0[nt][1] * iA0, c0[nt][0] * iA0);
        rB0[nt * 4 + tg] = cvt_h2(c0[nt][3] * iB0, c0[nt][2] * iB0);
        rA1[nt * 4 + tg] = cvt_h2(c1[nt][1] * iA1, c1[nt][0] * iA1);
        rB1[nt * 4 + tg] = cvt_h2(c1[nt][3] * iB1, c1[nt][2] * iB1);
    }
}

// ============================================================================
// Kernel B: fp16 MLP, grid 512 (one 128-row tile per CTA), single-stage smem.
// ============================================================================
constexpr int SMW1B = 128 * RPB;     // 34816
constexpr int SMW2B = 64 * RPB;      // 17408
constexpr int SMXB  = 128 * RPB;     // 34816
constexpr int MLP_SMEM = SMW1B + SMW2B + SMXB + (128 + 128 + 64 + 64) * 4;

__global__ __launch_bounds__(256) void mlp_kernel(float* __restrict__ out) {
    extern __shared__ __align__(16) char sm[];
    __half* sW1 = (__half*)sm;
    __half* sW2 = (__half*)(sm + SMW1B);
    __half* sX  = (__half*)(sm + SMW1B + SMW2B);
    float* sS1 = (float*)(sm + SMW1B + SMW2B + SMXB);
    float* sT1 = sS1 + 128;
    float* sS2 = sT1 + 128;
    float* sT2 = sS2 + 64;

    const int tid = threadIdx.x, wid = tid >> 5, lane = tid & 31;
    const int g = lane >> 2, tg = lane & 3;
    const int r0 = wid * 16;
    const int tile = blockIdx.x;

    const u32 bW1 = smem_u32(sW1), bW2 = smem_u32(sW2), bX = smem_u32(sX);

    for (int i = tid; i < 2048; i += 256) {
        int r = i >> 4, q = i & 15;
        cp16(bW1 + (u32)(r * RPB + q * 16), g_W1 + r * 128 + q * 8);
    }
    for (int i = tid; i < 1024; i += 256) {
        int r = i >> 4, q = i & 15;
        cp16(bW2 + (u32)(r * RPB + q * 16), g_W2 + r * 128 + q * 8);
    }
    for (int i = tid; i < 2048; i += 256) {
        int r = i >> 4, q = i & 15;
        cp16(bX + (u32)(r * RPB + q * 16),
             g_x16 + ((size_t)tile * 128 + r) * 128 + q * 8);
    }
    CP_COMMIT();
    if (tid < 128) { sS1[tid] = g_S1[tid]; sT1[tid] = g_T1[tid]; }
    if (tid < 64)  { sS2[tid] = g_S2[tid]; sT2[tid] = g_T2[tid]; }
    CP_WAIT0();
    __syncthreads();

    const u32 lrow4 = (u32)((lane & 7) * RPB + ((lane >> 3) & 1) * 16
                            + ((lane >> 4) & 1) * (8 * RPB));
    const u32 larow = (u32)((lane & 15) * RPB + (lane >> 4) * 16);

    float c1[16][4];
#pragma unroll
    for (int i = 0; i < 16; ++i)
#pragma unroll
        for (int j = 0; j < 4; ++j) c1[i][j] = 0.f;

#pragma unroll
    for (int ks = 0; ks < 8; ++ks) {
        u32 ah[4];
        ldsm_x4(ah, bX + (u32)(r0 * RPB + ks * 32) + larow);
        const u32 koff = (u32)(ks * 32);
#pragma unroll
        for (int ntp = 0; ntp < 8; ++ntp) {
            u32 bf[4];
            ldsm_x4(bf, bW1 + (u32)(ntp * 16 * RPB) + lrow4 + koff);
            mma_f16(c1[2 * ntp],     ah, bf[0], bf[1]);
            mma_f16(c1[2 * ntp + 1], ah, bf[2], bf[3]);
        }
    }

    u32 a2[8][4];
#pragma unroll
    for (int k2 = 0; k2 < 8; ++k2) {
        int nt0 = 2 * k2, nt1 = 2 * k2 + 1;
        int o0 = nt0 * 8 + 2 * tg, o1 = o0 + 1;
        int o2 = nt1 * 8 + 2 * tg, o3 = o2 + 1;
        float hA0 = fmaxf(fmaf(c1[nt0][0], sS1[o0], sT1[o0]), 0.f);
        float hA1 = fmaxf(fmaf(c1[nt0][1], sS1[o1], sT1[o1]), 0.f);
        float hB0 = fmaxf(fmaf(c1[nt0][2], sS1[o0], sT1[o0]), 0.f);
        float hB1 = fmaxf(fmaf(c1[nt0][3], sS1[o1], sT1[o1]), 0.f);
        float hA2 = fmaxf(fmaf(c1[nt1][0], sS1[o2], sT1[o2]), 0.f);
        float hA3 = fmaxf(fmaf(c1[nt1][1], sS1[o3], sT1[o3]), 0.f);
        float hB2 = fmaxf(fmaf(c1[nt1][2], sS1[o2], sT1[o2]), 0.f);
        float hB3 = fmaxf(fmaf(c1[nt1][3], sS1[o3], sT1[o3]), 0.f);
        a2[k2][0] = cvt_h2(hA1, hA0);
        a2[k2][1] = cvt_h2(hB1, hB0);
        a2[k2][2] = cvt_h2(hA3, hA2);
        a2[k2][3] = cvt_h2(hB3, hB2);
    }

    float c2[8][4];
#pragma unroll
    for (int i = 0; i < 8; ++i)
#pragma unroll
        for (int j = 0; j < 4; ++j) c2[i][j] = 0.f;

#pragma unroll
    for (int k2 = 0; k2 < 8; ++k2) {
        const u32 koff = (u32)(k2 * 32);
#pragma unroll
        for (int ntp = 0; ntp < 4; ++ntp) {
            u32 bf[4];
            ldsm_x4(bf, bW2 + (u32)(ntp * 16 * RPB) + lrow4 + koff);
            mma_f16(c2[2 * ntp],     a2[k2], bf[0], bf[1]);
            mma_f16(c2[2 * ntp + 1], a2[k2], bf[2], bf[3]);
        }
    }

    const size_t rowA = (size_t)tile * 128 + r0 + g;
    const size_t rowB = rowA + 8;
    float* oA = out + rowA * 64;
    float* oB = out + rowB * 64;
#pragma unroll
    for (int nt = 0; nt < 8; ++nt) {
        int j0 = nt * 8 + 2 * tg, j1 = j0 + 1;
        *(float2*)(oA + j0) = make_float2(fmaf(c2[nt][0], sS2[j0], sT2[j0]),
                                          fmaf(c2[nt][1], sS2[j1], sT2[j1]));
        *(float2*)(oB + j0) = make_float2(fmaf(c2[nt][2], sS2[j0], sT2[j0]),
                                          fmaf(c2[nt][3], sS2[j1], sT2[j1]));
    }
}

// ============================================================================
extern "C" void kernel_launch(void* const* d_in, const int* in_sizes, int n_in,
                              void* d_out, int out_size)
{
    const float* xyz_down  = (const float*)d_in[0];
    const float* xyz_up    = (const float*)d_in[1];
    const float* feat_down = (const float*)d_in[2];
    const float* feat_up   = (const float*)d_in[3];
    const float* W1  = (const float*)d_in[4];
    const float* b1  = (const float*)d_in[5];
    const float* g1  = (const float*)d_in[6];
    const float* be1 = (const float*)d_in[7];
    const float* mu1 = (const float*)d_in[8];
    const float* va1 = (const float*)d_in[9];
    const float* W2  = (const float*)d_in[10];
    const float* b2  = (const float*)d_in[11];
    const float* g2  = (const float*)d_in[12];
    const float* be2 = (const float*)d_in[13];
    const float* mu2 = (const float*)d_in[14];
    const float* va2 = (const float*)d_in[15];
    float* out = (float*)d_out;

    prep_feat<<<dim3(M_ / 64, B_), 256>>>(feat_down);
    prep_fu<<<4096, 256>>>(feat_up);
    prep_w<<<96, 256>>>(W1, b1, g1, be1, mu1, va1, W2, b2, g2, be2, mu2, va2);

    cudaFuncSetAttribute(interp_kernel,
                         cudaFuncAttributeMaxDynamicSharedMemorySize, INTERP_SMEM);
    interp_kernel<<<dim3(N_ / 128, B_), 128, INTERP_SMEM>>>(xyz_down, xyz_up);

    cudaFuncSetAttribute(mlp_kernel,
                         cudaFuncAttributeMaxDynamicSharedMemorySize, MLP_SMEM);
    mlp_kernel<<<512, 256, MLP_SMEM>>>(out);
}